// round 11
// baseline (speedup 1.0000x reference)
#include <cuda_runtime.h>
#include <cuda_bf16.h>
#include <math.h>
#include <stdint.h>

#define D 128
#define N_MAX 50048
#define TILE_N 128
#define MLP_THREADS 512
#define SAW 68   // smem row stride in 32-bit words (ldmatrix conflict-free)

// Scratch (device globals — no allocation allowed)
__device__ float g_deg[N_MAX];
__device__ float g_norm[N_MAX];
__device__ float g_agg[(size_t)N_MAX * D];

// ---------------------------------------------------------------------------
// bf16x2 / mma / ldmatrix helpers
// ---------------------------------------------------------------------------
__device__ __forceinline__ uint32_t pack_bf16x2(float v_lo, float v_hi) {
    uint32_t r;
    asm("cvt.rn.bf16x2.f32 %0, %1, %2;" : "=r"(r) : "f"(v_hi), "f"(v_lo));
    return r;
}
__device__ __forceinline__ void split2(float v0, float v1,
                                       uint32_t& hi, uint32_t& lo) {
    hi = pack_bf16x2(v0, v1);
    float h0 = __uint_as_float(hi << 16);
    float h1 = __uint_as_float(hi & 0xffff0000u);
    lo = pack_bf16x2(v0 - h0, v1 - h1);
}
__device__ __forceinline__ void mma_bf16(float d[4],
                                         uint32_t a0, uint32_t a1,
                                         uint32_t a2, uint32_t a3,
                                         uint32_t b0, uint32_t b1) {
    asm volatile(
        "mma.sync.aligned.m16n8k16.row.col.f32.bf16.bf16.f32 "
        "{%0,%1,%2,%3}, {%4,%5,%6,%7}, {%8,%9}, {%0,%1,%2,%3};"
        : "+f"(d[0]), "+f"(d[1]), "+f"(d[2]), "+f"(d[3])
        : "r"(a0), "r"(a1), "r"(a2), "r"(a3), "r"(b0), "r"(b1));
}
#define LDSM4(r0, r1, r2, r3, addr)                                         \
    asm volatile("ldmatrix.sync.aligned.m8n8.x4.shared.b16 "                \
                 "{%0,%1,%2,%3}, [%4];"                                     \
                 : "=r"(r0), "=r"(r1), "=r"(r2), "=r"(r3) : "r"(addr))

// ---------------------------------------------------------------------------
// 1) in-degree count over dst
// ---------------------------------------------------------------------------
__global__ void deg_kernel(const int* __restrict__ dst, int E) {
    int i = blockIdx.x * blockDim.x + threadIdx.x;
    if (i < E) atomicAdd(&g_deg[dst[i]], 1.0f);
}

// ---------------------------------------------------------------------------
// 2) norm = rsqrt(max(deg,1))
// ---------------------------------------------------------------------------
__global__ void norm_kernel(int N) {
    int i = blockIdx.x * blockDim.x + threadIdx.x;
    if (i < N) g_norm[i] = rsqrtf(fmaxf(g_deg[i], 1.0f));
}

// ---------------------------------------------------------------------------
// 3) SPMM: agg[dst] += x[src] * norm[src]  (one warp per edge, red.v4 scatter)
// ---------------------------------------------------------------------------
__global__ void spmm_kernel(const float* __restrict__ x,
                            const int* __restrict__ src,
                            const int* __restrict__ dst,
                            int E) {
    int t = blockIdx.x * blockDim.x + threadIdx.x;
    int e = t >> 5;
    int lane = t & 31;
    if (e >= E) return;
    int s = __ldg(&src[e]);
    int d = __ldg(&dst[e]);
    float ns = __ldg((const float*)&g_norm[s]);
    float4 v = __ldg(((const float4*)(x + (size_t)s * D)) + lane);
    v.x *= ns; v.y *= ns; v.z *= ns; v.w *= ns;
    float* p = &g_agg[(size_t)d * D + lane * 4];
    asm volatile("red.global.add.v4.f32 [%0], {%1, %2, %3, %4};"
                 :: "l"(p), "f"(v.x), "f"(v.y), "f"(v.z), "f"(v.w)
                 : "memory");
}

// ---------------------------------------------------------------------------
// bf16-split GEMM mainloop via ldmatrix: pure LDSM + HMMA.
//   Warp tile 32(m) x 32(n): acc = 32 floats, frags = 16 regs.
// ---------------------------------------------------------------------------
__device__ __forceinline__ void gemm_ldsm(uint32_t a_hi, uint32_t a_lo,
                                          uint32_t w_hi, uint32_t w_lo,
                                          float d[2][4][4]) {
    #pragma unroll
    for (int kb = 0; kb < 64; kb += 8) {    // 8 kpairs = k16 per step
        uint32_t bh[4][2], bl[4][2];
        LDSM4(bh[0][0], bh[0][1], bh[1][0], bh[1][1], w_hi + 4 * kb);
        LDSM4(bh[2][0], bh[2][1], bh[3][0], bh[3][1], w_hi + 4 * (16 * SAW + kb));
        LDSM4(bl[0][0], bl[0][1], bl[1][0], bl[1][1], w_lo + 4 * kb);
        LDSM4(bl[2][0], bl[2][1], bl[3][0], bl[3][1], w_lo + 4 * (16 * SAW + kb));
        #pragma unroll
        for (int mi = 0; mi < 2; mi++) {
            uint32_t ah0, ah1, ah2, ah3, al0, al1, al2, al3;
            LDSM4(ah0, ah1, ah2, ah3, a_hi + 4 * (mi * 16 * SAW + kb));
            LDSM4(al0, al1, al2, al3, a_lo + 4 * (mi * 16 * SAW + kb));
            #pragma unroll
            for (int ni = 0; ni < 4; ni++) {
                mma_bf16(d[mi][ni], ah0, ah1, ah2, ah3, bh[ni][0], bh[ni][1]);
                mma_bf16(d[mi][ni], ah0, ah1, ah2, ah3, bl[ni][0], bl[ni][1]);
                mma_bf16(d[mi][ni], al0, al1, al2, al3, bh[ni][0], bh[ni][1]);
            }
        }
    }
}

// ---------------------------------------------------------------------------
// 4) Fused 2-layer MLP on tensor cores (bf16 2-way split, 3 terms, LDSM).
//    512 threads; warp grid 4(m) x 4(n); warp tile 32x32; tile 128x128.
// ---------------------------------------------------------------------------
__global__ void __launch_bounds__(MLP_THREADS, 1)
mlp_kernel(const float* __restrict__ wc, const float* __restrict__ bc,
           const float* __restrict__ wl, const float* __restrict__ bl,
           float* __restrict__ out, int N) {
    extern __shared__ uint32_t sm[];
    uint32_t* s_ahi = sm;                      // [128][SAW]
    uint32_t* s_alo = s_ahi + 128 * SAW;       // [128][SAW]
    uint32_t* s_whi = s_alo + 128 * SAW;       // [128][SAW]
    uint32_t* s_wlo = s_whi + 128 * SAW;       // [128][SAW]

    const int tid = threadIdx.x;
    const int lane = tid & 31;
    const int wid = tid >> 5;
    const int warp_m = wid >> 2;   // 0..3
    const int warp_n = wid & 3;    // 0..3
    const int g = lane >> 2;       // 0..7
    const int q = lane & 3;        // 0..3
    const int n0 = blockIdx.x * TILE_N;

    uint32_t sbase;
    asm("{ .reg .u64 t; cvta.to.shared.u64 t, %1; cvt.u32.u64 %0, t; }"
        : "=r"(sbase) : "l"(sm));

    // ldmatrix per-lane patterns (in words)
    const int a_lane = (lane & 15) * SAW + (lane >> 4) * 4;
    const int b_lane = ((lane >> 4) * 8 + (lane & 7)) * SAW + ((lane >> 3) & 1) * 4;

    const uint32_t a_hi = sbase + 4 * ((warp_m * 32) * SAW + a_lane);
    const uint32_t a_lo = a_hi + 4 * (128 * SAW);
    const uint32_t w_hi = sbase + 4 * (256 * SAW + (warp_n * 32) * SAW + b_lane);
    const uint32_t w_lo = w_hi + 4 * (128 * SAW);

    // ---- fill w1: [o][kpair], split hi/lo ----
    for (int i = tid; i < 128 * 64; i += MLP_THREADS) {
        int o = i >> 6, kp = i & 63;
        float2 w = *(const float2*)&wc[o * 128 + kp * 2];
        uint32_t hi, lo;
        split2(w.x, w.y, hi, lo);
        s_whi[o * SAW + kp] = hi;
        s_wlo[o * SAW + kp] = lo;
    }
    // ---- fill input tile: agg[n][k] * norm[n], split hi/lo ----
    for (int i = tid; i < TILE_N * 64; i += MLP_THREADS) {
        int n = i >> 6, kp = i & 63;
        int gn = n0 + n;
        float2 v = make_float2(0.f, 0.f);
        float nn = 0.f;
        if (gn < N) {
            v = *(const float2*)&g_agg[(size_t)gn * 128 + kp * 2];
            nn = g_norm[gn];
        }
        uint32_t hi, lo;
        split2(v.x * nn, v.y * nn, hi, lo);
        s_ahi[n * SAW + kp] = hi;
        s_alo[n * SAW + kp] = lo;
    }
    __syncthreads();

    float d[2][4][4];

    // ================= GEMM 1 =================
    #pragma unroll
    for (int mi = 0; mi < 2; mi++)
        #pragma unroll
        for (int ni = 0; ni < 4; ni++)
            #pragma unroll
            for (int p = 0; p < 4; p++) d[mi][ni][p] = 0.0f;

    gemm_ldsm(a_hi, a_lo, w_hi, w_lo, d);

    __syncthreads();   // everyone done reading s_a / s_w

    // ---- epilogue 1: h = relu(d + bc), split & write back to s_a ----
    {
        #pragma unroll
        for (int ni = 0; ni < 4; ni++) {
            int col = warp_n * 32 + ni * 8 + q * 2;
            int kp = col >> 1;
            float2 b = *(const float2*)&bc[col];
            #pragma unroll
            for (int mi = 0; mi < 2; mi++) {
                int row = warp_m * 32 + mi * 16 + g;
                float h0 = fmaxf(d[mi][ni][0] + b.x, 0.0f);
                float h1 = fmaxf(d[mi][ni][1] + b.y, 0.0f);
                float h2 = fmaxf(d[mi][ni][2] + b.x, 0.0f);
                float h3 = fmaxf(d[mi][ni][3] + b.y, 0.0f);
                uint32_t hi, lo;
                split2(h0, h1, hi, lo);
                s_ahi[row * SAW + kp] = hi;
                s_alo[row * SAW + kp] = lo;
                split2(h2, h3, hi, lo);
                s_ahi[(row + 8) * SAW + kp] = hi;
                s_alo[(row + 8) * SAW + kp] = lo;
            }
        }
    }
    // ---- fill w2 split hi/lo ----
    for (int i = tid; i < 128 * 64; i += MLP_THREADS) {
        int o = i >> 6, kp = i & 63;
        float2 w = *(const float2*)&wl[o * 128 + kp * 2];
        uint32_t hi, lo;
        split2(w.x, w.y, hi, lo);
        s_whi[o * SAW + kp] = hi;
        s_wlo[o * SAW + kp] = lo;
    }
    __syncthreads();

    // ================= GEMM 2 =================
    #pragma unroll
    for (int mi = 0; mi < 2; mi++)
        #pragma unroll
        for (int ni = 0; ni < 4; ni++)
            #pragma unroll
            for (int p = 0; p < 4; p++) d[mi][ni][p] = 0.0f;

    gemm_ldsm(a_hi, a_lo, w_hi, w_lo, d);

    // ---- epilogue 2: out = relu(d + bl) -> gmem ----
    {
        #pragma unroll
        for (int ni = 0; ni < 4; ni++) {
            int col = warp_n * 32 + ni * 8 + q * 2;
            float2 b = *(const float2*)&bl[col];
            #pragma unroll
            for (int mi = 0; mi < 2; mi++) {
                int row = warp_m * 32 + mi * 16 + g;
                int gn0 = n0 + row;
                int gn1 = gn0 + 8;
                if (gn0 < N) {
                    float2 v = make_float2(fmaxf(d[mi][ni][0] + b.x, 0.0f),
                                           fmaxf(d[mi][ni][1] + b.y, 0.0f));
                    *(float2*)&out[(size_t)gn0 * 128 + col] = v;
                }
                if (gn1 < N) {
                    float2 v = make_float2(fmaxf(d[mi][ni][2] + b.x, 0.0f),
                                           fmaxf(d[mi][ni][3] + b.y, 0.0f));
                    *(float2*)&out[(size_t)gn1 * 128 + col] = v;
                }
            }
        }
    }
}

// ---------------------------------------------------------------------------
extern "C" void kernel_launch(void* const* d_in, const int* in_sizes, int n_in,
                              void* d_out, int out_size) {
    const float* x    = (const float*)d_in[0];
    const int*   src  = (const int*)  d_in[1];
    const int*   dst  = (const int*)  d_in[2];
    const float* wc   = (const float*)d_in[3];
    const float* bc   = (const float*)d_in[4];
    const float* wl   = (const float*)d_in[5];
    const float* bl   = (const float*)d_in[6];
    float* out = (float*)d_out;

    const int N = in_sizes[0] / D;
    const int E = in_sizes[1];

    void* p_deg = nullptr;
    void* p_agg = nullptr;
    cudaGetSymbolAddress(&p_deg, g_deg);
    cudaGetSymbolAddress(&p_agg, g_agg);
    cudaMemsetAsync(p_deg, 0, (size_t)N * sizeof(float));
    cudaMemsetAsync(p_agg, 0, (size_t)N * D * sizeof(float));

    deg_kernel<<<(E + 255) / 256, 256>>>(dst, E);
    norm_kernel<<<(N + 255) / 256, 256>>>(N);

    long long spmm_threads = (long long)E * 32;
    int spmm_blocks = (int)((spmm_threads + 255) / 256);
    spmm_kernel<<<spmm_blocks, 256>>>(x, src, dst, E);

    const int smem_bytes = 512 * SAW * sizeof(uint32_t);  // ~136KB
    cudaFuncSetAttribute(mlp_kernel, cudaFuncAttributeMaxDynamicSharedMemorySize, smem_bytes);
    int mlp_blocks = (N + TILE_N - 1) / TILE_N;
    mlp_kernel<<<mlp_blocks, MLP_THREADS, smem_bytes>>>(wc, bc, wl, bl, out, N);
}

// round 12
// speedup vs baseline: 1.4942x; 1.4942x over previous
#include <cuda_runtime.h>
#include <cuda_bf16.h>
#include <math.h>
#include <stdint.h>

#define D 128
#define N_MAX 50176
#define E_MAX 800000
#define TILE_N 128
#define MLP_THREADS 256
#define SAW 68   // smem row stride in 32-bit words
#define SCAN_BLK 256

// Scratch (device globals — no allocation allowed)
__device__ int   g_degi[N_MAX];
__device__ int   g_bsum[256];
__device__ int   g_boff[257];
__device__ int   g_off[N_MAX + 1];
__device__ int   g_cur[N_MAX];
__device__ int   g_csr[E_MAX];
__device__ float g_norm[N_MAX];
__device__ float g_agg[(size_t)N_MAX * D];

// ---------------------------------------------------------------------------
// bf16x2 / mma helpers
// ---------------------------------------------------------------------------
__device__ __forceinline__ uint32_t pack_bf16x2(float v_lo, float v_hi) {
    uint32_t r;
    asm("cvt.rn.bf16x2.f32 %0, %1, %2;" : "=r"(r) : "f"(v_hi), "f"(v_lo));
    return r;
}
__device__ __forceinline__ void split2(float v0, float v1,
                                       uint32_t& hi, uint32_t& lo) {
    hi = pack_bf16x2(v0, v1);
    float h0 = __uint_as_float(hi << 16);
    float h1 = __uint_as_float(hi & 0xffff0000u);
    lo = pack_bf16x2(v0 - h0, v1 - h1);
}
__device__ __forceinline__ void mma_bf16(float d[4],
                                         uint32_t a0, uint32_t a1,
                                         uint32_t a2, uint32_t a3,
                                         uint32_t b0, uint32_t b1) {
    asm volatile(
        "mma.sync.aligned.m16n8k16.row.col.f32.bf16.bf16.f32 "
        "{%0,%1,%2,%3}, {%4,%5,%6,%7}, {%8,%9}, {%0,%1,%2,%3};"
        : "+f"(d[0]), "+f"(d[1]), "+f"(d[2]), "+f"(d[3])
        : "r"(a0), "r"(a1), "r"(a2), "r"(a3), "r"(b0), "r"(b1));
}

// ---------------------------------------------------------------------------
// 1) int in-degree histogram (4 edges/thread, no-return reduction)
// ---------------------------------------------------------------------------
__global__ void deg_kernel(const int* __restrict__ dst, int E) {
    int i = (blockIdx.x * blockDim.x + threadIdx.x) * 4;
    if (i + 4 <= E) {
        int4 d4 = *(const int4*)(dst + i);
        asm volatile("red.global.add.u32 [%0], %1;" :: "l"(&g_degi[d4.x]), "r"(1) : "memory");
        asm volatile("red.global.add.u32 [%0], %1;" :: "l"(&g_degi[d4.y]), "r"(1) : "memory");
        asm volatile("red.global.add.u32 [%0], %1;" :: "l"(&g_degi[d4.z]), "r"(1) : "memory");
        asm volatile("red.global.add.u32 [%0], %1;" :: "l"(&g_degi[d4.w]), "r"(1) : "memory");
    } else {
        for (; i < E; i++)
            asm volatile("red.global.add.u32 [%0], %1;" :: "l"(&g_degi[dst[i]]), "r"(1) : "memory");
    }
}

// ---------------------------------------------------------------------------
// 2a) per-block degree sums
// ---------------------------------------------------------------------------
__global__ void scan1_kernel(int N) {
    __shared__ int red[8];
    int i = blockIdx.x * SCAN_BLK + threadIdx.x;
    int v = (i < N) ? g_degi[i] : 0;
    #pragma unroll
    for (int o = 16; o > 0; o >>= 1) v += __shfl_down_sync(~0u, v, o);
    if ((threadIdx.x & 31) == 0) red[threadIdx.x >> 5] = v;
    __syncthreads();
    if (threadIdx.x < 8) {
        int s = red[threadIdx.x];
        #pragma unroll
        for (int o = 4; o > 0; o >>= 1) s += __shfl_down_sync(0xffu, s, o);
        if (threadIdx.x == 0) g_bsum[blockIdx.x] = s;
    }
}

// ---------------------------------------------------------------------------
// 2b) single-block exclusive scan of block sums (nb <= 256)
// ---------------------------------------------------------------------------
__global__ void scan2_kernel(int nb, int N) {
    __shared__ int ws[8];
    int t = threadIdx.x;
    int v = (t < nb) ? g_bsum[t] : 0;
    int lane = t & 31, w = t >> 5;
    // inclusive scan within warp
    int s = v;
    #pragma unroll
    for (int o = 1; o < 32; o <<= 1) {
        int u = __shfl_up_sync(~0u, s, o);
        if (lane >= o) s += u;
    }
    if (lane == 31) ws[w] = s;
    __syncthreads();
    if (t < 8) {
        int u = ws[t];
        #pragma unroll
        for (int o = 1; o < 8; o <<= 1) {
            int z = __shfl_up_sync(0xffu, u, o);
            if (t >= o) u += z;
        }
        ws[t] = u;
    }
    __syncthreads();
    int base = (w > 0) ? ws[w - 1] : 0;
    int incl = base + s;
    if (t < nb) g_boff[t] = incl - v;   // exclusive
    if (t == nb - 1) g_off[N] = incl;   // total edge count
}

// ---------------------------------------------------------------------------
// 2c) local exclusive scan per block + offsets, cursors, norm
// ---------------------------------------------------------------------------
__global__ void scan3_kernel(int N) {
    __shared__ int ws[8];
    int i = blockIdx.x * SCAN_BLK + threadIdx.x;
    int t = threadIdx.x, lane = t & 31, w = t >> 5;
    int v = (i < N) ? g_degi[i] : 0;
    int s = v;
    #pragma unroll
    for (int o = 1; o < 32; o <<= 1) {
        int u = __shfl_up_sync(~0u, s, o);
        if (lane >= o) s += u;
    }
    if (lane == 31) ws[w] = s;
    __syncthreads();
    if (t < 8) {
        int u = ws[t];
        #pragma unroll
        for (int o = 1; o < 8; o <<= 1) {
            int z = __shfl_up_sync(0xffu, u, o);
            if (t >= o) u += z;
        }
        ws[t] = u;
    }
    __syncthreads();
    int base = ((w > 0) ? ws[w - 1] : 0) + g_boff[blockIdx.x];
    int ex = base + s - v;
    if (i < N) {
        g_off[i] = ex;
        g_cur[i] = ex;
        g_norm[i] = rsqrtf(fmaxf((float)v, 1.0f));
    }
}

// ---------------------------------------------------------------------------
// 3) scatter edges into CSR (by dst), storing src ids
// ---------------------------------------------------------------------------
__global__ void scatter_kernel(const int* __restrict__ src,
                               const int* __restrict__ dst, int E) {
    int i = blockIdx.x * blockDim.x + threadIdx.x;
    if (i < E) {
        int d = dst[i];
        int pos = atomicAdd(&g_cur[d], 1);
        g_csr[pos] = src[i];
    }
}

// ---------------------------------------------------------------------------
// 4) segment reduce: one warp per dst node (measured 35us in round 3)
// ---------------------------------------------------------------------------
__global__ void segreduce_kernel(const float* __restrict__ x, int N) {
    int w = (blockIdx.x * blockDim.x + threadIdx.x) >> 5;
    int lane = threadIdx.x & 31;
    if (w >= N) return;

    const int beg = g_off[w];
    const int end = g_off[w + 1];
    const float4* x4 = (const float4*)x;

    float4 acc = make_float4(0.f, 0.f, 0.f, 0.f);
    int e = beg;
    for (; e + 2 <= end; e += 2) {
        int s0 = __ldg(&g_csr[e]);
        int s1 = __ldg(&g_csr[e + 1]);
        float n0 = __ldg(&g_norm[s0]);
        float n1 = __ldg(&g_norm[s1]);
        float4 v0 = __ldg(&x4[(size_t)s0 * 32 + lane]);
        float4 v1 = __ldg(&x4[(size_t)s1 * 32 + lane]);
        acc.x = fmaf(v0.x, n0, acc.x); acc.y = fmaf(v0.y, n0, acc.y);
        acc.z = fmaf(v0.z, n0, acc.z); acc.w = fmaf(v0.w, n0, acc.w);
        acc.x = fmaf(v1.x, n1, acc.x); acc.y = fmaf(v1.y, n1, acc.y);
        acc.z = fmaf(v1.z, n1, acc.z); acc.w = fmaf(v1.w, n1, acc.w);
    }
    if (e < end) {
        int s0 = __ldg(&g_csr[e]);
        float n0 = __ldg(&g_norm[s0]);
        float4 v0 = __ldg(&x4[(size_t)s0 * 32 + lane]);
        acc.x = fmaf(v0.x, n0, acc.x); acc.y = fmaf(v0.y, n0, acc.y);
        acc.z = fmaf(v0.z, n0, acc.z); acc.w = fmaf(v0.w, n0, acc.w);
    }

    float nd = g_norm[w];
    acc.x *= nd; acc.y *= nd; acc.z *= nd; acc.w *= nd;
    ((float4*)g_agg)[(size_t)w * 32 + lane] = acc;
}

// ---------------------------------------------------------------------------
// 5) Fused 2-layer MLP (round-6 version verbatim: bf16 3-term, scalar LDS).
//    agg is already fully normalized -> plain copy in the fill.
// ---------------------------------------------------------------------------
__device__ __forceinline__ void gemm_bf16x3(const uint32_t* __restrict__ s_ahi,
                                            const uint32_t* __restrict__ s_alo,
                                            const uint32_t* __restrict__ s_whi,
                                            const uint32_t* __restrict__ s_wlo,
                                            float d[4][4][4],
                                            int g, int q, int warp_m, int warp_n) {
    #pragma unroll 2
    for (int kb = 0; kb < 64; kb += 8) {
        uint32_t bh[4][2], bl[4][2];
        #pragma unroll
        for (int ni = 0; ni < 4; ni++) {
            int o = warp_n * 32 + ni * 8 + g;
            int r0 = o * SAW + kb + q;
            bh[ni][0] = s_whi[r0];
            bh[ni][1] = s_whi[r0 + 4];
            bl[ni][0] = s_wlo[r0];
            bl[ni][1] = s_wlo[r0 + 4];
        }
        #pragma unroll
        for (int mi = 0; mi < 4; mi++) {
            int row = warp_m * 64 + mi * 16 + g;
            int r0 = row * SAW + kb + q;
            int r1 = (row + 8) * SAW + kb + q;
            uint32_t ah0 = s_ahi[r0],     ah1 = s_ahi[r1];
            uint32_t ah2 = s_ahi[r0 + 4], ah3 = s_ahi[r1 + 4];
            uint32_t al0 = s_alo[r0],     al1 = s_alo[r1];
            uint32_t al2 = s_alo[r0 + 4], al3 = s_alo[r1 + 4];
            #pragma unroll
            for (int ni = 0; ni < 4; ni++) {
                mma_bf16(d[mi][ni], ah0, ah1, ah2, ah3, bh[ni][0], bh[ni][1]);
                mma_bf16(d[mi][ni], ah0, ah1, ah2, ah3, bl[ni][0], bl[ni][1]);
                mma_bf16(d[mi][ni], al0, al1, al2, al3, bh[ni][0], bh[ni][1]);
            }
        }
    }
}

__global__ void __launch_bounds__(MLP_THREADS, 1)
mlp_kernel(const float* __restrict__ wc, const float* __restrict__ bc,
           const float* __restrict__ wl, const float* __restrict__ bl,
           float* __restrict__ out, int N) {
    extern __shared__ uint32_t sm[];
    uint32_t* s_ahi = sm;
    uint32_t* s_alo = s_ahi + 128 * SAW;
    uint32_t* s_whi = s_alo + 128 * SAW;
    uint32_t* s_wlo = s_whi + 128 * SAW;

    const int tid = threadIdx.x;
    const int lane = tid & 31;
    const int wid = tid >> 5;
    const int warp_m = wid >> 2;
    const int warp_n = wid & 3;
    const int g = lane >> 2;
    const int q = lane & 3;
    const int n0 = blockIdx.x * TILE_N;

    for (int i = tid; i < 128 * 64; i += MLP_THREADS) {
        int o = i >> 6, kp = i & 63;
        float2 w = *(const float2*)&wc[o * 128 + kp * 2];
        uint32_t hi, lo;
        split2(w.x, w.y, hi, lo);
        s_whi[o * SAW + kp] = hi;
        s_wlo[o * SAW + kp] = lo;
    }
    for (int i = tid; i < TILE_N * 64; i += MLP_THREADS) {
        int n = i >> 6, kp = i & 63;
        int gn = n0 + n;
        float2 v = make_float2(0.f, 0.f);
        if (gn < N) v = *(const float2*)&g_agg[(size_t)gn * 128 + kp * 2];
        uint32_t hi, lo;
        split2(v.x, v.y, hi, lo);
        s_ahi[n * SAW + kp] = hi;
        s_alo[n * SAW + kp] = lo;
    }
    __syncthreads();

    float d[4][4][4];

    #pragma unroll
    for (int mi = 0; mi < 4; mi++)
        #pragma unroll
        for (int ni = 0; ni < 4; ni++)
            #pragma unroll
            for (int p = 0; p < 4; p++) d[mi][ni][p] = 0.0f;

    gemm_bf16x3(s_ahi, s_alo, s_whi, s_wlo, d, g, q, warp_m, warp_n);

    __syncthreads();

    {
        #pragma unroll
        for (int ni = 0; ni < 4; ni++) {
            int col = warp_n * 32 + ni * 8 + q * 2;
            int kp = col >> 1;
            float2 b = *(const float2*)&bc[col];
            #pragma unroll
            for (int mi = 0; mi < 4; mi++) {
                int row = warp_m * 64 + mi * 16 + g;
                float h0 = fmaxf(d[mi][ni][0] + b.x, 0.0f);
                float h1 = fmaxf(d[mi][ni][1] + b.y, 0.0f);
                float h2 = fmaxf(d[mi][ni][2] + b.x, 0.0f);
                float h3 = fmaxf(d[mi][ni][3] + b.y, 0.0f);
                uint32_t hi, lo;
                split2(h0, h1, hi, lo);
                s_ahi[row * SAW + kp] = hi;
                s_alo[row * SAW + kp] = lo;
                split2(h2, h3, hi, lo);
                s_ahi[(row + 8) * SAW + kp] = hi;
                s_alo[(row + 8) * SAW + kp] = lo;
            }
        }
    }
    for (int i = tid; i < 128 * 64; i += MLP_THREADS) {
        int o = i >> 6, kp = i & 63;
        float2 w = *(const float2*)&wl[o * 128 + kp * 2];
        uint32_t hi, lo;
        split2(w.x, w.y, hi, lo);
        s_whi[o * SAW + kp] = hi;
        s_wlo[o * SAW + kp] = lo;
    }
    __syncthreads();

    #pragma unroll
    for (int mi = 0; mi < 4; mi++)
        #pragma unroll
        for (int ni = 0; ni < 4; ni++)
            #pragma unroll
            for (int p = 0; p < 4; p++) d[mi][ni][p] = 0.0f;

    gemm_bf16x3(s_ahi, s_alo, s_whi, s_wlo, d, g, q, warp_m, warp_n);

    {
        #pragma unroll
        for (int ni = 0; ni < 4; ni++) {
            int col = warp_n * 32 + ni * 8 + q * 2;
            float2 b = *(const float2*)&bl[col];
            #pragma unroll
            for (int mi = 0; mi < 4; mi++) {
                int row = warp_m * 64 + mi * 16 + g;
                int gn0 = n0 + row;
                int gn1 = gn0 + 8;
                if (gn0 < N) {
                    float2 v = make_float2(fmaxf(d[mi][ni][0] + b.x, 0.0f),
                                           fmaxf(d[mi][ni][1] + b.y, 0.0f));
                    *(float2*)&out[(size_t)gn0 * 128 + col] = v;
                }
                if (gn1 < N) {
                    float2 v = make_float2(fmaxf(d[mi][ni][2] + b.x, 0.0f),
                                           fmaxf(d[mi][ni][3] + b.y, 0.0f));
                    *(float2*)&out[(size_t)gn1 * 128 + col] = v;
                }
            }
        }
    }
}

// ---------------------------------------------------------------------------
extern "C" void kernel_launch(void* const* d_in, const int* in_sizes, int n_in,
                              void* d_out, int out_size) {
    const float* x    = (const float*)d_in[0];
    const int*   src  = (const int*)  d_in[1];
    const int*   dst  = (const int*)  d_in[2];
    const float* wc   = (const float*)d_in[3];
    const float* bc   = (const float*)d_in[4];
    const float* wl   = (const float*)d_in[5];
    const float* bl   = (const float*)d_in[6];
    float* out = (float*)d_out;

    const int N = in_sizes[0] / D;
    const int E = in_sizes[1];
    const int nb = (N + SCAN_BLK - 1) / SCAN_BLK;   // 196 for N=50000

    void* p_degi = nullptr;
    cudaGetSymbolAddress(&p_degi, g_degi);
    cudaMemsetAsync(p_degi, 0, (size_t)N * sizeof(int));

    int deg_threads = (E + 3) / 4;
    deg_kernel<<<(deg_threads + 255) / 256, 256>>>(dst, E);

    scan1_kernel<<<nb, SCAN_BLK>>>(N);
    scan2_kernel<<<1, 256>>>(nb, N);
    scan3_kernel<<<nb, SCAN_BLK>>>(N);

    scatter_kernel<<<(E + 255) / 256, 256>>>(src, dst, E);

    long long sr_threads = (long long)N * 32;
    int sr_blocks = (int)((sr_threads + 255) / 256);
    segreduce_kernel<<<sr_blocks, 256>>>(x, N);

    const int smem_bytes = 512 * SAW * sizeof(uint32_t);  // ~136KB
    cudaFuncSetAttribute(mlp_kernel, cudaFuncAttributeMaxDynamicSharedMemorySize, smem_bytes);
    int mlp_blocks = (N + TILE_N - 1) / TILE_N;
    mlp_kernel<<<mlp_blocks, MLP_THREADS, smem_bytes>>>(wc, bc, wl, bl, out, N);
}

// round 14
// speedup vs baseline: 1.5570x; 1.0420x over previous
#include <cuda_runtime.h>
#include <cuda_bf16.h>
#include <math.h>
#include <stdint.h>

#define D 128
#define N_MAX 50176
#define E_MAX 800000
#define TILE_N 128
#define MLP_THREADS 256
#define SAW 68   // smem row stride in 32-bit words
#define SCAN_BLK 256

// Scratch (device globals — no allocation allowed)
__device__ int      g_degi[N_MAX];
__device__ int      g_bsum[256];
__device__ int      g_boff[257];
__device__ int      g_off[N_MAX + 1];
__device__ int      g_cur[N_MAX];
__device__ int      g_csr[E_MAX];
__device__ float    g_norm[N_MAX];
__device__ uint32_t g_ahi[(size_t)N_MAX * 64];   // activations, bf16x2 hi
__device__ uint32_t g_alo[(size_t)N_MAX * 64];   // activations, bf16x2 lo
__device__ uint32_t g_whi1[128 * 64], g_wlo1[128 * 64];
__device__ uint32_t g_whi2[128 * 64], g_wlo2[128 * 64];

// ---------------------------------------------------------------------------
// bf16x2 / mma helpers
// ---------------------------------------------------------------------------
__device__ __forceinline__ uint32_t pack_bf16x2(float v_lo, float v_hi) {
    uint32_t r;
    asm("cvt.rn.bf16x2.f32 %0, %1, %2;" : "=r"(r) : "f"(v_hi), "f"(v_lo));
    return r;
}
__device__ __forceinline__ void split2(float v0, float v1,
                                       uint32_t& hi, uint32_t& lo) {
    hi = pack_bf16x2(v0, v1);
    float h0 = __uint_as_float(hi << 16);
    float h1 = __uint_as_float(hi & 0xffff0000u);
    lo = pack_bf16x2(v0 - h0, v1 - h1);
}
__device__ __forceinline__ void mma_bf16(float d[4],
                                         uint32_t a0, uint32_t a1,
                                         uint32_t a2, uint32_t a3,
                                         uint32_t b0, uint32_t b1) {
    asm volatile(
        "mma.sync.aligned.m16n8k16.row.col.f32.bf16.bf16.f32 "
        "{%0,%1,%2,%3}, {%4,%5,%6,%7}, {%8,%9}, {%0,%1,%2,%3};"
        : "+f"(d[0]), "+f"(d[1]), "+f"(d[2]), "+f"(d[3])
        : "r"(a0), "r"(a1), "r"(a2), "r"(a3), "r"(b0), "r"(b1));
}

// ---------------------------------------------------------------------------
// 0) pre-split both weight matrices into bf16x2 hi/lo ([o][kpair] layout)
// ---------------------------------------------------------------------------
__global__ void wsplit_kernel(const float* __restrict__ wc,
                              const float* __restrict__ wl) {
    int i = blockIdx.x * blockDim.x + threadIdx.x;   // 0 .. 2*8192-1
    if (i < 128 * 64) {
        float2 w = *(const float2*)&wc[i * 2];
        uint32_t hi, lo;
        split2(w.x, w.y, hi, lo);
        g_whi1[i] = hi;
        g_wlo1[i] = lo;
    } else if (i < 2 * 128 * 64) {
        int j = i - 128 * 64;
        float2 w = *(const float2*)&wl[j * 2];
        uint32_t hi, lo;
        split2(w.x, w.y, hi, lo);
        g_whi2[j] = hi;
        g_wlo2[j] = lo;
    }
}

// ---------------------------------------------------------------------------
// 1) int in-degree histogram (4 edges/thread, no-return reduction)
// ---------------------------------------------------------------------------
__global__ void deg_kernel(const int* __restrict__ dst, int E) {
    int i = (blockIdx.x * blockDim.x + threadIdx.x) * 4;
    if (i + 4 <= E) {
        int4 d4 = *(const int4*)(dst + i);
        asm volatile("red.global.add.u32 [%0], %1;" :: "l"(&g_degi[d4.x]), "r"(1) : "memory");
        asm volatile("red.global.add.u32 [%0], %1;" :: "l"(&g_degi[d4.y]), "r"(1) : "memory");
        asm volatile("red.global.add.u32 [%0], %1;" :: "l"(&g_degi[d4.z]), "r"(1) : "memory");
        asm volatile("red.global.add.u32 [%0], %1;" :: "l"(&g_degi[d4.w]), "r"(1) : "memory");
    } else {
        for (; i < E; i++)
            asm volatile("red.global.add.u32 [%0], %1;" :: "l"(&g_degi[dst[i]]), "r"(1) : "memory");
    }
}

// ---------------------------------------------------------------------------
// 2a) per-block degree sums
// ---------------------------------------------------------------------------
__global__ void scan1_kernel(int N) {
    __shared__ int red[8];
    int i = blockIdx.x * SCAN_BLK + threadIdx.x;
    int v = (i < N) ? g_degi[i] : 0;
    #pragma unroll
    for (int o = 16; o > 0; o >>= 1) v += __shfl_down_sync(~0u, v, o);
    if ((threadIdx.x & 31) == 0) red[threadIdx.x >> 5] = v;
    __syncthreads();
    if (threadIdx.x < 8) {
        int s = red[threadIdx.x];
        #pragma unroll
        for (int o = 4; o > 0; o >>= 1) s += __shfl_down_sync(0xffu, s, o);
        if (threadIdx.x == 0) g_bsum[blockIdx.x] = s;
    }
}

// ---------------------------------------------------------------------------
// 2b) single-block exclusive scan of block sums (nb <= 256)
// ---------------------------------------------------------------------------
__global__ void scan2_kernel(int nb, int N) {
    __shared__ int ws[8];
    int t = threadIdx.x;
    int v = (t < nb) ? g_bsum[t] : 0;
    int lane = t & 31, w = t >> 5;
    int s = v;
    #pragma unroll
    for (int o = 1; o < 32; o <<= 1) {
        int u = __shfl_up_sync(~0u, s, o);
        if (lane >= o) s += u;
    }
    if (lane == 31) ws[w] = s;
    __syncthreads();
    if (t < 8) {
        int u = ws[t];
        #pragma unroll
        for (int o = 1; o < 8; o <<= 1) {
            int z = __shfl_up_sync(0xffu, u, o);
            if (t >= o) u += z;
        }
        ws[t] = u;
    }
    __syncthreads();
    int base = (w > 0) ? ws[w - 1] : 0;
    int incl = base + s;
    if (t < nb) g_boff[t] = incl - v;
    if (t == nb - 1) g_off[N] = incl;
}

// ---------------------------------------------------------------------------
// 2c) local exclusive scan per block + offsets, cursors, norm
// ---------------------------------------------------------------------------
__global__ void scan3_kernel(int N) {
    __shared__ int ws[8];
    int i = blockIdx.x * SCAN_BLK + threadIdx.x;
    int t = threadIdx.x, lane = t & 31, w = t >> 5;
    int v = (i < N) ? g_degi[i] : 0;
    int s = v;
    #pragma unroll
    for (int o = 1; o < 32; o <<= 1) {
        int u = __shfl_up_sync(~0u, s, o);
        if (lane >= o) s += u;
    }
    if (lane == 31) ws[w] = s;
    __syncthreads();
    if (t < 8) {
        int u = ws[t];
        #pragma unroll
        for (int o = 1; o < 8; o <<= 1) {
            int z = __shfl_up_sync(0xffu, u, o);
            if (t >= o) u += z;
        }
        ws[t] = u;
    }
    __syncthreads();
    int base = ((w > 0) ? ws[w - 1] : 0) + g_boff[blockIdx.x];
    int ex = base + s - v;
    if (i < N) {
        g_off[i] = ex;
        g_cur[i] = ex;
        g_norm[i] = rsqrtf(fmaxf((float)v, 1.0f));
    }
}

// ---------------------------------------------------------------------------
// 3) scatter edges into CSR (by dst), storing src ids
// ---------------------------------------------------------------------------
__global__ void scatter_kernel(const int* __restrict__ src,
                               const int* __restrict__ dst, int E) {
    int i = blockIdx.x * blockDim.x + threadIdx.x;
    if (i < E) {
        int d = dst[i];
        int pos = atomicAdd(&g_cur[d], 1);
        g_csr[pos] = src[i];
    }
}

// ---------------------------------------------------------------------------
// 4) segment reduce: one warp per dst node; writes PRE-SPLIT bf16x2 hi/lo.
// ---------------------------------------------------------------------------
__global__ void segreduce_kernel(const float* __restrict__ x, int N) {
    int w = (blockIdx.x * blockDim.x + threadIdx.x) >> 5;
    int lane = threadIdx.x & 31;
    if (w >= N) return;

    const int beg = g_off[w];
    const int end = g_off[w + 1];
    const float4* x4 = (const float4*)x;

    float4 acc = make_float4(0.f, 0.f, 0.f, 0.f);
    int e = beg;
    for (; e + 2 <= end; e += 2) {
        int s0 = __ldg(&g_csr[e]);
        int s1 = __ldg(&g_csr[e + 1]);
        float n0 = __ldg(&g_norm[s0]);
        float n1 = __ldg(&g_norm[s1]);
        float4 v0 = __ldg(&x4[(size_t)s0 * 32 + lane]);
        float4 v1 = __ldg(&x4[(size_t)s1 * 32 + lane]);
        acc.x = fmaf(v0.x, n0, acc.x); acc.y = fmaf(v0.y, n0, acc.y);
        acc.z = fmaf(v0.z, n0, acc.z); acc.w = fmaf(v0.w, n0, acc.w);
        acc.x = fmaf(v1.x, n1, acc.x); acc.y = fmaf(v1.y, n1, acc.y);
        acc.z = fmaf(v1.z, n1, acc.z); acc.w = fmaf(v1.w, n1, acc.w);
    }
    if (e < end) {
        int s0 = __ldg(&g_csr[e]);
        float n0 = __ldg(&g_norm[s0]);
        float4 v0 = __ldg(&x4[(size_t)s0 * 32 + lane]);
        acc.x = fmaf(v0.x, n0, acc.x); acc.y = fmaf(v0.y, n0, acc.y);
        acc.z = fmaf(v0.z, n0, acc.z); acc.w = fmaf(v0.w, n0, acc.w);
    }

    float nd = g_norm[w];
    acc.x *= nd; acc.y *= nd; acc.z *= nd; acc.w *= nd;

    uint32_t hi0, lo0, hi1, lo1;
    split2(acc.x, acc.y, hi0, lo0);
    split2(acc.z, acc.w, hi1, lo1);
    ((uint2*)g_ahi)[(size_t)w * 32 + lane] = make_uint2(hi0, hi1);
    ((uint2*)g_alo)[(size_t)w * 32 + lane] = make_uint2(lo0, lo1);
}

// ---------------------------------------------------------------------------
// bf16-split GEMM mainloop (round-6, proven)
// ---------------------------------------------------------------------------
__device__ __forceinline__ void gemm_bf16x3(const uint32_t* __restrict__ s_ahi,
                                            const uint32_t* __restrict__ s_alo,
                                            const uint32_t* __restrict__ s_whi,
                                            const uint32_t* __restrict__ s_wlo,
                                            float d[4][4][4],
                                            int g, int q, int warp_m, int warp_n) {
    #pragma unroll 2
    for (int kb = 0; kb < 64; kb += 8) {
        uint32_t bh[4][2], bl[4][2];
        #pragma unroll
        for (int ni = 0; ni < 4; ni++) {
            int o = warp_n * 32 + ni * 8 + g;
            int r0 = o * SAW + kb + q;
            bh[ni][0] = s_whi[r0];
            bh[ni][1] = s_whi[r0 + 4];
            bl[ni][0] = s_wlo[r0];
            bl[ni][1] = s_wlo[r0 + 4];
        }
        #pragma unroll
        for (int mi = 0; mi < 4; mi++) {
            int row = warp_m * 64 + mi * 16 + g;
            int r0 = row * SAW + kb + q;
            int r1 = (row + 8) * SAW + kb + q;
            uint32_t ah0 = s_ahi[r0],     ah1 = s_ahi[r1];
            uint32_t ah2 = s_ahi[r0 + 4], ah3 = s_ahi[r1 + 4];
            uint32_t al0 = s_alo[r0],     al1 = s_alo[r1];
            uint32_t al2 = s_alo[r0 + 4], al3 = s_alo[r1 + 4];
            #pragma unroll
            for (int ni = 0; ni < 4; ni++) {
                mma_bf16(d[mi][ni], ah0, ah1, ah2, ah3, bh[ni][0], bh[ni][1]);
                mma_bf16(d[mi][ni], ah0, ah1, ah2, ah3, bl[ni][0], bl[ni][1]);
                mma_bf16(d[mi][ni], al0, al1, al2, al3, bh[ni][0], bh[ni][1]);
            }
        }
    }
}

// ---------------------------------------------------------------------------
// 5) Fused 2-layer MLP — fills are now pure vectorized copies.
// ---------------------------------------------------------------------------
__global__ void __launch_bounds__(MLP_THREADS, 1)
mlp_kernel(const float* __restrict__ bc, const float* __restrict__ bl,
           float* __restrict__ out, int N) {
    extern __shared__ uint32_t sm[];
    uint32_t* s_ahi = sm;
    uint32_t* s_alo = s_ahi + 128 * SAW;
    uint32_t* s_whi = s_alo + 128 * SAW;
    uint32_t* s_wlo = s_whi + 128 * SAW;

    const int tid = threadIdx.x;
    const int lane = tid & 31;
    const int wid = tid >> 5;
    const int warp_m = wid >> 2;
    const int warp_n = wid & 3;
    const int g = lane >> 2;
    const int q = lane & 3;
    const int n0 = blockIdx.x * TILE_N;

    // ---- fill w1 + input tile: pure uint4 copies ----
    for (int i = tid; i < 128 * 16; i += MLP_THREADS) {   // 16 uint4 per row
        int o = i >> 4, c = (i & 15) * 4;
        *(uint4*)&s_whi[o * SAW + c] = *(const uint4*)&g_whi1[o * 64 + c];
        *(uint4*)&s_wlo[o * SAW + c] = *(const uint4*)&g_wlo1[o * 64 + c];
    }
    for (int i = tid; i < TILE_N * 16; i += MLP_THREADS) {
        int n = i >> 4, c = (i & 15) * 4;
        int gn = n0 + n;
        uint4 hi = make_uint4(0, 0, 0, 0), lo = make_uint4(0, 0, 0, 0);
        if (gn < N) {
            hi = *(const uint4*)&g_ahi[(size_t)gn * 64 + c];
            lo = *(const uint4*)&g_alo[(size_t)gn * 64 + c];
        }
        *(uint4*)&s_ahi[n * SAW + c] = hi;
        *(uint4*)&s_alo[n * SAW + c] = lo;
    }
    __syncthreads();

    float d[4][4][4];

    #pragma unroll
    for (int mi = 0; mi < 4; mi++)
        #pragma unroll
        for (int ni = 0; ni < 4; ni++)
            #pragma unroll
            for (int p = 0; p < 4; p++) d[mi][ni][p] = 0.0f;

    gemm_bf16x3(s_ahi, s_alo, s_whi, s_wlo, d, g, q, warp_m, warp_n);

    __syncthreads();

    // ---- epilogue 1: h = relu(d + bc), split & write back to s_a ----
    {
        #pragma unroll
        for (int ni = 0; ni < 4; ni++) {
            int col = warp_n * 32 + ni * 8 + q * 2;
            int kp = col >> 1;
            float2 b = *(const float2*)&bc[col];
            #pragma unroll
            for (int mi = 0; mi < 4; mi++) {
                int row = warp_m * 64 + mi * 16 + g;
                float h0 = fmaxf(d[mi][ni][0] + b.x, 0.0f);
                float h1 = fmaxf(d[mi][ni][1] + b.y, 0.0f);
                float h2 = fmaxf(d[mi][ni][2] + b.x, 0.0f);
                float h3 = fmaxf(d[mi][ni][3] + b.y, 0.0f);
                uint32_t hi, lo;
                split2(h0, h1, hi, lo);
                s_ahi[row * SAW + kp] = hi;
                s_alo[row * SAW + kp] = lo;
                split2(h2, h3, hi, lo);
                s_ahi[(row + 8) * SAW + kp] = hi;
                s_alo[(row + 8) * SAW + kp] = lo;
            }
        }
    }
    // ---- fill w2: pure uint4 copy ----
    for (int i = tid; i < 128 * 16; i += MLP_THREADS) {
        int o = i >> 4, c = (i & 15) * 4;
        *(uint4*)&s_whi[o * SAW + c] = *(const uint4*)&g_whi2[o * 64 + c];
        *(uint4*)&s_wlo[o * SAW + c] = *(const uint4*)&g_wlo2[o * 64 + c];
    }
    __syncthreads();

    #pragma unroll
    for (int mi = 0; mi < 4; mi++)
        #pragma unroll
        for (int ni = 0; ni < 4; ni++)
            #pragma unroll
            for (int p = 0; p < 4; p++) d[mi][ni][p] = 0.0f;

    gemm_bf16x3(s_ahi, s_alo, s_whi, s_wlo, d, g, q, warp_m, warp_n);

    // ---- epilogue 2: out = relu(d + bl) -> gmem ----
    {
        #pragma unroll
        for (int ni = 0; ni < 4; ni++) {
            int col = warp_n * 32 + ni * 8 + q * 2;
            float2 b = *(const float2*)&bl[col];
            #pragma unroll
            for (int mi = 0; mi < 4; mi++) {
                int row = warp_m * 64 + mi * 16 + g;
                int gn0 = n0 + row;
                int gn1 = gn0 + 8;
                if (gn0 < N) {
                    float2 v = make_float2(fmaxf(d[mi][ni][0] + b.x, 0.0f),
                                           fmaxf(d[mi][ni][1] + b.y, 0.0f));
                    *(float2*)&out[(size_t)gn0 * 128 + col] = v;
                }
                if (gn1 < N) {
                    float2 v = make_float2(fmaxf(d[mi][ni][2] + b.x, 0.0f),
                                           fmaxf(d[mi][ni][3] + b.y, 0.0f));
                    *(float2*)&out[(size_t)gn1 * 128 + col] = v;
                }
            }
        }
    }
}

// ---------------------------------------------------------------------------
extern "C" void kernel_launch(void* const* d_in, const int* in_sizes, int n_in,
                              void* d_out, int out_size) {
    const float* x    = (const float*)d_in[0];
    const int*   src  = (const int*)  d_in[1];
    const int*   dst  = (const int*)  d_in[2];
    const float* wc   = (const float*)d_in[3];
    const float* bc   = (const float*)d_in[4];
    const float* wl   = (const float*)d_in[5];
    const float* bl   = (const float*)d_in[6];
    float* out = (float*)d_out;

    const int N = in_sizes[0] / D;
    const int E = in_sizes[1];
    const int nb = (N + SCAN_BLK - 1) / SCAN_BLK;

    void* p_degi = nullptr;
    cudaGetSymbolAddress(&p_degi, g_degi);
    cudaMemsetAsync(p_degi, 0, (size_t)N * sizeof(int));

    wsplit_kernel<<<(2 * 128 * 64 + 255) / 256, 256>>>(wc, wl);

    int deg_threads = (E + 3) / 4;
    deg_kernel<<<(deg_threads + 255) / 256, 256>>>(dst, E);

    scan1_kernel<<<nb, SCAN_BLK>>>(N);
    scan2_kernel<<<1, 256>>>(nb, N);
    scan3_kernel<<<nb, SCAN_BLK>>>(N);

    scatter_kernel<<<(E + 255) / 256, 256>>>(src, dst, E);

    long long sr_threads = (long long)N * 32;
    int sr_blocks = (int)((sr_threads + 255) / 256);
    segreduce_kernel<<<sr_blocks, 256>>>(x, N);

    const int smem_bytes = 512 * SAW * sizeof(uint32_t);  // ~136KB
    cudaFuncSetAttribute(mlp_kernel, cudaFuncAttributeMaxDynamicSharedMemorySize, smem_bytes);
    int mlp_blocks = (N + TILE_N - 1) / TILE_N;
    mlp_kernel<<<mlp_blocks, MLP_THREADS, smem_bytes>>>(bc, bl, out, N);
}

// round 15
// speedup vs baseline: 1.6763x; 1.0766x over previous
#include <cuda_runtime.h>
#include <cuda_bf16.h>
#include <math.h>
#include <stdint.h>

#define D 128
#define N_MAX 50176
#define E_MAX 800000
#define TILE_N 64
#define MLP_THREADS 256
#define SAW 68   // smem row stride in 32-bit words
#define SCAN_BLK 256

// Scratch (device globals — zero-initialized at load; g_degi invariant:
// zero at entry of every kernel_launch call, re-zeroed by scan3).
__device__ int      g_degi[N_MAX];
__device__ int      g_bsum[256];
__device__ int      g_off[N_MAX + 1];
__device__ int      g_cur[N_MAX];
__device__ int      g_csr[E_MAX];
__device__ float    g_norm[N_MAX];
__device__ uint32_t g_ahi[(size_t)N_MAX * 64];   // activations, bf16x2 hi
__device__ uint32_t g_alo[(size_t)N_MAX * 64];   // activations, bf16x2 lo
__device__ uint32_t g_whi1[128 * 64], g_wlo1[128 * 64];
__device__ uint32_t g_whi2[128 * 64], g_wlo2[128 * 64];

// ---------------------------------------------------------------------------
// bf16x2 / mma helpers
// ---------------------------------------------------------------------------
__device__ __forceinline__ uint32_t pack_bf16x2(float v_lo, float v_hi) {
    uint32_t r;
    asm("cvt.rn.bf16x2.f32 %0, %1, %2;" : "=r"(r) : "f"(v_hi), "f"(v_lo));
    return r;
}
__device__ __forceinline__ void split2(float v0, float v1,
                                       uint32_t& hi, uint32_t& lo) {
    hi = pack_bf16x2(v0, v1);
    float h0 = __uint_as_float(hi << 16);
    float h1 = __uint_as_float(hi & 0xffff0000u);
    lo = pack_bf16x2(v0 - h0, v1 - h1);
}
__device__ __forceinline__ void mma_bf16(float d[4],
                                         uint32_t a0, uint32_t a1,
                                         uint32_t a2, uint32_t a3,
                                         uint32_t b0, uint32_t b1) {
    asm volatile(
        "mma.sync.aligned.m16n8k16.row.col.f32.bf16.bf16.f32 "
        "{%0,%1,%2,%3}, {%4,%5,%6,%7}, {%8,%9}, {%0,%1,%2,%3};"
        : "+f"(d[0]), "+f"(d[1]), "+f"(d[2]), "+f"(d[3])
        : "r"(a0), "r"(a1), "r"(a2), "r"(a3), "r"(b0), "r"(b1));
}

// ---------------------------------------------------------------------------
// 0) pre-split both weight matrices into bf16x2 hi/lo ([o][kpair] layout)
// ---------------------------------------------------------------------------
__global__ void wsplit_kernel(const float* __restrict__ wc,
                              const float* __restrict__ wl) {
    int i = blockIdx.x * blockDim.x + threadIdx.x;
    if (i < 128 * 64) {
        float2 w = *(const float2*)&wc[i * 2];
        uint32_t hi, lo;
        split2(w.x, w.y, hi, lo);
        g_whi1[i] = hi;
        g_wlo1[i] = lo;
    } else if (i < 2 * 128 * 64) {
        int j = i - 128 * 64;
        float2 w = *(const float2*)&wl[j * 2];
        uint32_t hi, lo;
        split2(w.x, w.y, hi, lo);
        g_whi2[j] = hi;
        g_wlo2[j] = lo;
    }
}

// ---------------------------------------------------------------------------
// 1) int in-degree histogram (4 edges/thread, no-return reduction)
// ---------------------------------------------------------------------------
__global__ void deg_kernel(const int* __restrict__ dst, int E) {
    int i = (blockIdx.x * blockDim.x + threadIdx.x) * 4;
    if (i + 4 <= E) {
        int4 d4 = *(const int4*)(dst + i);
        asm volatile("red.global.add.u32 [%0], %1;" :: "l"(&g_degi[d4.x]), "r"(1) : "memory");
        asm volatile("red.global.add.u32 [%0], %1;" :: "l"(&g_degi[d4.y]), "r"(1) : "memory");
        asm volatile("red.global.add.u32 [%0], %1;" :: "l"(&g_degi[d4.z]), "r"(1) : "memory");
        asm volatile("red.global.add.u32 [%0], %1;" :: "l"(&g_degi[d4.w]), "r"(1) : "memory");
    } else {
        for (; i < E; i++)
            asm volatile("red.global.add.u32 [%0], %1;" :: "l"(&g_degi[dst[i]]), "r"(1) : "memory");
    }
}

// ---------------------------------------------------------------------------
// 2a) per-block degree sums
// ---------------------------------------------------------------------------
__global__ void scan1_kernel(int N) {
    __shared__ int red[8];
    int i = blockIdx.x * SCAN_BLK + threadIdx.x;
    int v = (i < N) ? g_degi[i] : 0;
    #pragma unroll
    for (int o = 16; o > 0; o >>= 1) v += __shfl_down_sync(~0u, v, o);
    if ((threadIdx.x & 31) == 0) red[threadIdx.x >> 5] = v;
    __syncthreads();
    if (threadIdx.x < 8) {
        int s = red[threadIdx.x];
        #pragma unroll
        for (int o = 4; o > 0; o >>= 1) s += __shfl_down_sync(0xffu, s, o);
        if (threadIdx.x == 0) g_bsum[blockIdx.x] = s;
    }
}

// ---------------------------------------------------------------------------
// 2b) merged: every block scans the block sums in smem, then does its local
//     scan; writes offsets/cursors/norm and RE-ZEROES g_degi for next call.
// ---------------------------------------------------------------------------
__global__ void scan3_kernel(int N, int nb) {
    __shared__ int ws[8];
    __shared__ int s_base[257];
    int t = threadIdx.x, lane = t & 31, w = t >> 5;

    // ---- phase A: exclusive scan of g_bsum[0..nb) (nb <= 256) ----
    {
        int v = (t < nb) ? g_bsum[t] : 0;
        int s = v;
        #pragma unroll
        for (int o = 1; o < 32; o <<= 1) {
            int u = __shfl_up_sync(~0u, s, o);
            if (lane >= o) s += u;
        }
        if (lane == 31) ws[w] = s;
        __syncthreads();
        if (t < 8) {
            int u = ws[t];
            #pragma unroll
            for (int o = 1; o < 8; o <<= 1) {
                int z = __shfl_up_sync(0xffu, u, o);
                if (t >= o) u += z;
            }
            ws[t] = u;
        }
        __syncthreads();
        int incl = ((w > 0) ? ws[w - 1] : 0) + s;
        s_base[t] = incl - v;                 // exclusive
        if (t == nb - 1) s_base[256] = incl;  // total
        __syncthreads();
    }
    const int blkbase = s_base[blockIdx.x];
    const int total = s_base[256];

    // ---- phase B: local exclusive scan of degi ----
    int i = blockIdx.x * SCAN_BLK + t;
    int v = (i < N) ? g_degi[i] : 0;
    int s = v;
    #pragma unroll
    for (int o = 1; o < 32; o <<= 1) {
        int u = __shfl_up_sync(~0u, s, o);
        if (lane >= o) s += u;
    }
    __syncthreads();   // ws reuse
    if (lane == 31) ws[w] = s;
    __syncthreads();
    if (t < 8) {
        int u = ws[t];
        #pragma unroll
        for (int o = 1; o < 8; o <<= 1) {
            int z = __shfl_up_sync(0xffu, u, o);
            if (t >= o) u += z;
        }
        ws[t] = u;
    }
    __syncthreads();
    int ex = blkbase + ((w > 0) ? ws[w - 1] : 0) + s - v;
    if (i < N) {
        g_off[i] = ex;
        g_cur[i] = ex;
        g_norm[i] = rsqrtf(fmaxf((float)v, 1.0f));
        g_degi[i] = 0;   // restore zero invariant for next call
    }
    if (blockIdx.x == 0 && t == 0) g_off[N] = total;
}

// ---------------------------------------------------------------------------
// 3) scatter edges into CSR (4 edges/thread)
// ---------------------------------------------------------------------------
__global__ void scatter_kernel(const int* __restrict__ src,
                               const int* __restrict__ dst, int E) {
    int i = (blockIdx.x * blockDim.x + threadIdx.x) * 4;
    if (i + 4 <= E) {
        int4 s4 = *(const int4*)(src + i);
        int4 d4 = *(const int4*)(dst + i);
        g_csr[atomicAdd(&g_cur[d4.x], 1)] = s4.x;
        g_csr[atomicAdd(&g_cur[d4.y], 1)] = s4.y;
        g_csr[atomicAdd(&g_cur[d4.z], 1)] = s4.z;
        g_csr[atomicAdd(&g_cur[d4.w], 1)] = s4.w;
    } else {
        for (; i < E; i++)
            g_csr[atomicAdd(&g_cur[dst[i]], 1)] = src[i];
    }
}

// ---------------------------------------------------------------------------
// 4) segment reduce: one warp per dst node; writes PRE-SPLIT bf16x2 hi/lo.
// ---------------------------------------------------------------------------
__global__ void segreduce_kernel(const float* __restrict__ x, int N) {
    int w = (blockIdx.x * blockDim.x + threadIdx.x) >> 5;
    int lane = threadIdx.x & 31;
    if (w >= N) return;

    const int beg = g_off[w];
    const int end = g_off[w + 1];
    const float4* x4 = (const float4*)x;

    float4 acc = make_float4(0.f, 0.f, 0.f, 0.f);
    int e = beg;
    for (; e + 2 <= end; e += 2) {
        int s0 = __ldg(&g_csr[e]);
        int s1 = __ldg(&g_csr[e + 1]);
        float n0 = __ldg(&g_norm[s0]);
        float n1 = __ldg(&g_norm[s1]);
        float4 v0 = __ldg(&x4[(size_t)s0 * 32 + lane]);
        float4 v1 = __ldg(&x4[(size_t)s1 * 32 + lane]);
        acc.x = fmaf(v0.x, n0, acc.x); acc.y = fmaf(v0.y, n0, acc.y);
        acc.z = fmaf(v0.z, n0, acc.z); acc.w = fmaf(v0.w, n0, acc.w);
        acc.x = fmaf(v1.x, n1, acc.x); acc.y = fmaf(v1.y, n1, acc.y);
        acc.z = fmaf(v1.z, n1, acc.z); acc.w = fmaf(v1.w, n1, acc.w);
    }
    if (e < end) {
        int s0 = __ldg(&g_csr[e]);
        float n0 = __ldg(&g_norm[s0]);
        float4 v0 = __ldg(&x4[(size_t)s0 * 32 + lane]);
        acc.x = fmaf(v0.x, n0, acc.x); acc.y = fmaf(v0.y, n0, acc.y);
        acc.z = fmaf(v0.z, n0, acc.z); acc.w = fmaf(v0.w, n0, acc.w);
    }

    float nd = g_norm[w];
    acc.x *= nd; acc.y *= nd; acc.z *= nd; acc.w *= nd;

    uint32_t hi0, lo0, hi1, lo1;
    split2(acc.x, acc.y, hi0, lo0);
    split2(acc.z, acc.w, hi1, lo1);
    ((uint2*)g_ahi)[(size_t)w * 32 + lane] = make_uint2(hi0, hi1);
    ((uint2*)g_alo)[(size_t)w * 32 + lane] = make_uint2(lo0, lo1);
}

// ---------------------------------------------------------------------------
// bf16-split GEMM mainloop (warp tile 32x32 -> acc d[2][4][4])
// ---------------------------------------------------------------------------
__device__ __forceinline__ void gemm_bf16x3(const uint32_t* __restrict__ s_ahi,
                                            const uint32_t* __restrict__ s_alo,
                                            const uint32_t* __restrict__ s_whi,
                                            const uint32_t* __restrict__ s_wlo,
                                            float d[2][4][4],
                                            int g, int q, int warp_m, int warp_n) {
    #pragma unroll 2
    for (int kb = 0; kb < 64; kb += 8) {
        uint32_t bh[4][2], bl[4][2];
        #pragma unroll
        for (int ni = 0; ni < 4; ni++) {
            int o = warp_n * 32 + ni * 8 + g;
            int r0 = o * SAW + kb + q;
            bh[ni][0] = s_whi[r0];
            bh[ni][1] = s_whi[r0 + 4];
            bl[ni][0] = s_wlo[r0];
            bl[ni][1] = s_wlo[r0 + 4];
        }
        #pragma unroll
        for (int mi = 0; mi < 2; mi++) {
            int row = warp_m * 32 + mi * 16 + g;
            int r0 = row * SAW + kb + q;
            int r1 = (row + 8) * SAW + kb + q;
            uint32_t ah0 = s_ahi[r0],     ah1 = s_ahi[r1];
            uint32_t ah2 = s_ahi[r0 + 4], ah3 = s_ahi[r1 + 4];
            uint32_t al0 = s_alo[r0],     al1 = s_alo[r1];
            uint32_t al2 = s_alo[r0 + 4], al3 = s_alo[r1 + 4];
            #pragma unroll
            for (int ni = 0; ni < 4; ni++) {
                mma_bf16(d[mi][ni], ah0, ah1, ah2, ah3, bh[ni][0], bh[ni][1]);
                mma_bf16(d[mi][ni], ah0, ah1, ah2, ah3, bl[ni][0], bl[ni][1]);
                mma_bf16(d[mi][ni], al0, al1, al2, al3, bh[ni][0], bh[ni][1]);
            }
        }
    }
}

// ---------------------------------------------------------------------------
// 5) Fused 2-layer MLP — tile 64 nodes, 104KB smem -> 2 CTAs/SM.
// ---------------------------------------------------------------------------
__global__ void __launch_bounds__(MLP_THREADS)
mlp_kernel(const float* __restrict__ bc, const float* __restrict__ bl,
           float* __restrict__ out, int N) {
    extern __shared__ uint32_t sm[];
    uint32_t* s_ahi = sm;                         // [64][SAW]
    uint32_t* s_alo = s_ahi + TILE_N * SAW;       // [64][SAW]
    uint32_t* s_whi = s_alo + TILE_N * SAW;       // [128][SAW]
    uint32_t* s_wlo = s_whi + 128 * SAW;          // [128][SAW]

    const int tid = threadIdx.x;
    const int lane = tid & 31;
    const int wid = tid >> 5;
    const int warp_m = wid >> 2;   // 0..1
    const int warp_n = wid & 3;    // 0..3
    const int g = lane >> 2;
    const int q = lane & 3;
    const int n0 = blockIdx.x * TILE_N;

    // ---- fill w1 + input tile: pure uint4 copies ----
    for (int i = tid; i < 128 * 16; i += MLP_THREADS) {
        int o = i >> 4, c = (i & 15) * 4;
        *(uint4*)&s_whi[o * SAW + c] = *(const uint4*)&g_whi1[o * 64 + c];
        *(uint4*)&s_wlo[o * SAW + c] = *(const uint4*)&g_wlo1[o * 64 + c];
    }
    for (int i = tid; i < TILE_N * 16; i += MLP_THREADS) {
        int n = i >> 4, c = (i & 15) * 4;
        int gn = n0 + n;
        uint4 hi = make_uint4(0, 0, 0, 0), lo = make_uint4(0, 0, 0, 0);
        if (gn < N) {
            hi = *(const uint4*)&g_ahi[(size_t)gn * 64 + c];
            lo = *(const uint4*)&g_alo[(size_t)gn * 64 + c];
        }
        *(uint4*)&s_ahi[n * SAW + c] = hi;
        *(uint4*)&s_alo[n * SAW + c] = lo;
    }
    __syncthreads();

    float d[2][4][4];

    #pragma unroll
    for (int mi = 0; mi < 2; mi++)
        #pragma unroll
        for (int ni = 0; ni < 4; ni++)
            #pragma unroll
            for (int p = 0; p < 4; p++) d[mi][ni][p] = 0.0f;

    gemm_bf16x3(s_ahi, s_alo, s_whi, s_wlo, d, g, q, warp_m, warp_n);

    __syncthreads();

    // ---- epilogue 1: h = relu(d + bc), split & write back to s_a ----
    {
        #pragma unroll
        for (int ni = 0; ni < 4; ni++) {
            int col = warp_n * 32 + ni * 8 + q * 2;
            int kp = col >> 1;
            float2 b = *(const float2*)&bc[col];
            #pragma unroll
            for (int mi = 0; mi < 2; mi++) {
                int row = warp_m * 32 + mi * 16 + g;
                float h0 = fmaxf(d[mi][ni][0] + b.x, 0.0f);
                float h1 = fmaxf(d[mi][ni][1] + b.y, 0.0f);
                float h2 = fmaxf(d[mi][ni][2] + b.x, 0.0f);
                float h3 = fmaxf(d[mi][ni][3] + b.y, 0.0f);
                uint32_t hi, lo;
                split2(h0, h1, hi, lo);
                s_ahi[row * SAW + kp] = hi;
                s_alo[row * SAW + kp] = lo;
                split2(h2, h3, hi, lo);
                s_ahi[(row + 8) * SAW + kp] = hi;
                s_alo[(row + 8) * SAW + kp] = lo;
            }
        }
    }
    // ---- fill w2: pure uint4 copy ----
    for (int i = tid; i < 128 * 16; i += MLP_THREADS) {
        int o = i >> 4, c = (i & 15) * 4;
        *(uint4*)&s_whi[o * SAW + c] = *(const uint4*)&g_whi2[o * 64 + c];
        *(uint4*)&s_wlo[o * SAW + c] = *(const uint4*)&g_wlo2[o * 64 + c];
    }
    __syncthreads();

    #pragma unroll
    for (int mi = 0; mi < 2; mi++)
        #pragma unroll
        for (int ni = 0; ni < 4; ni++)
            #pragma unroll
            for (int p = 0; p < 4; p++) d[mi][ni][p] = 0.0f;

    gemm_bf16x3(s_ahi, s_alo, s_whi, s_wlo, d, g, q, warp_m, warp_n);

    // ---- epilogue 2: out = relu(d + bl) -> gmem ----
    {
        #pragma unroll
        for (int ni = 0; ni < 4; ni++) {
            int col = warp_n * 32 + ni * 8 + q * 2;
            float2 b = *(const float2*)&bl[col];
            #pragma unroll
            for (int mi = 0; mi < 2; mi++) {
                int row = warp_m * 32 + mi * 16 + g;
                int gn0 = n0 + row;
                int gn1 = gn0 + 8;
                if (gn0 < N) {
                    float2 v = make_float2(fmaxf(d[mi][ni][0] + b.x, 0.0f),
                                           fmaxf(d[mi][ni][1] + b.y, 0.0f));
                    *(float2*)&out[(size_t)gn0 * 128 + col] = v;
                }
                if (gn1 < N) {
                    float2 v = make_float2(fmaxf(d[mi][ni][2] + b.x, 0.0f),
                                           fmaxf(d[mi][ni][3] + b.y, 0.0f));
                    *(float2*)&out[(size_t)gn1 * 128 + col] = v;
                }
            }
        }
    }
}

// ---------------------------------------------------------------------------
extern "C" void kernel_launch(void* const* d_in, const int* in_sizes, int n_in,
                              void* d_out, int out_size) {
    const float* x    = (const float*)d_in[0];
    const int*   src  = (const int*)  d_in[1];
    const int*   dst  = (const int*)  d_in[2];
    const float* wc   = (const float*)d_in[3];
    const float* bc   = (const float*)d_in[4];
    const float* wl   = (const float*)d_in[5];
    const float* bl   = (const float*)d_in[6];
    float* out = (float*)d_out;

    const int N = in_sizes[0] / D;
    const int E = in_sizes[1];
    const int nb = (N + SCAN_BLK - 1) / SCAN_BLK;

    wsplit_kernel<<<(2 * 128 * 64 + 255) / 256, 256>>>(wc, wl);

    int deg_threads = (E + 3) / 4;
    deg_kernel<<<(deg_threads + 255) / 256, 256>>>(dst, E);

    scan1_kernel<<<nb, SCAN_BLK>>>(N);
    scan3_kernel<<<nb, SCAN_BLK>>>(N, nb);

    scatter_kernel<<<(deg_threads + 255) / 256, 256>>>(src, dst, E);

    long long sr_threads = (long long)N * 32;
    int sr_blocks = (int)((sr_threads + 255) / 256);
    segreduce_kernel<<<sr_blocks, 256>>>(x, N);

    const int smem_bytes = (2 * TILE_N + 2 * 128) * SAW * sizeof(uint32_t); // ~104KB
    cudaFuncSetAttribute(mlp_kernel, cudaFuncAttributeMaxDynamicSharedMemorySize, smem_bytes);
    int mlp_blocks = (N + TILE_N - 1) / TILE_N;
    mlp_kernel<<<mlp_blocks, MLP_THREADS, smem_bytes>>>(bc, bl, out, N);
}